// round 14
// baseline (speedup 1.0000x reference)
#include <cuda_runtime.h>
#include <cuda_fp16.h>
#include <math.h>
#include <stdint.h>

// ---------------- problem constants ----------------
#define Nn 262144
#define Dd 64
#define Kk 64
#define TPB 256
#define GRID 296                 // persistent CTAs (2/SM x 148)
#define NCH (Nn/32)              // 8192 m32 chunks
#define LOG2PI_F 1.83787706640934548356f
#define EXP2_F 7.389056098930650f     // exp(2) = exp(-prior_logvar_0)
#define LOG2E_F 1.44269504088896340736f

// ---------------- smem layout (bytes, dynamic) ----------------
#define OFF_B     0               // 8*4*32 float4 = 16384
#define OFF_STG   16384           // 8 warps * 16*68 floats = 34816
#define OFF_OFFS  51200           // 64 f32
#define OFF_LPI   51456           // 64 f32 (natural-log pi table)
#define OFF_LPI2  51712           // 64 f32 (lpi * log2e)
#define OFF_WBG   51968
#define OFF_PHI   52224
#define OFF_SCR   52480           // 256 f32
#define SMEM_BYTES 53504

// ---------------- device globals ----------------
__device__ double g_lse;
__device__ unsigned int g_count;
__device__ unsigned int g_tile;

__device__ __forceinline__ void mma16(float c[4], const uint32_t a[4],
                                      uint32_t b0, uint32_t b1) {
    asm volatile("mma.sync.aligned.m16n8k16.row.col.f32.f16.f16.f32 "
        "{%0,%1,%2,%3},{%4,%5,%6,%7},{%8,%9},{%0,%1,%2,%3};"
        : "+f"(c[0]), "+f"(c[1]), "+f"(c[2]), "+f"(c[3])
        : "r"(a[0]), "r"(a[1]), "r"(a[2]), "r"(a[3]), "r"(b0), "r"(b1));
}
__device__ __forceinline__ uint32_t h2sq(uint32_t a) {
    __half2 h = *reinterpret_cast<__half2*>(&a);
    __half2 q = __hmul2(h, h);
    return *reinterpret_cast<uint32_t*>(&q);
}
__device__ __forceinline__ uint32_t f2h2(float lo, float hi) {
    __half2 h = __floats2half2_rn(lo, hi);
    return *reinterpret_cast<uint32_t*>(&h);
}
__device__ __forceinline__ __half2 ex2_h2(float z0, float z1) {
    __half2 z = __floats2half2_rn(z0, z1);
    uint32_t zi = *reinterpret_cast<uint32_t*>(&z), r;
    asm("ex2.approx.f16x2 %0, %1;" : "=r"(r) : "r"(zi));
    return *reinterpret_cast<__half2*>(&r);
}

// batched X fragment load for one m32 chunk (16 LDG.64, full MLP)
__device__ __forceinline__ void loadX(const float* __restrict__ X, int row0,
                                      int g, int t4, float2 v[4][4]) {
    const float2* Xg = (const float2*)X + (size_t)(row0 + g) * 32 + t4;
    #pragma unroll
    for (int ks = 0; ks < 4; ks++) {
        v[ks][0] = Xg[8 * ks];               // row g
        v[ks][1] = Xg[256 + 8 * ks];         // row g+8
        v[ks][2] = Xg[512 + 8 * ks];         // row g+16
        v[ks][3] = Xg[768 + 8 * ks];         // row g+24
    }
    #pragma unroll
    for (int ks = 0; ks < 2; ks++) {
        // second half-columns (+4 float2) for all four rows
        v[ks*2+0][0] = v[ks*2+0][0];         // (kept shape; loads below)
    }
}

// ---------------------------------------------------------------------------
__global__ void __launch_bounds__(TPB, 2)
gmm_kernel(const float* __restrict__ X,
           const float* __restrict__ u_noise,
           const float* __restrict__ phi_logits,
           const float* __restrict__ q_mu,
           const float* __restrict__ q_logvar,
           const float* __restrict__ pi_logits,
           const float* __restrict__ prior_p,
           float* __restrict__ out)
{
    extern __shared__ char smraw[];
    float4* B_s    = (float4*)(smraw + OFF_B);
    float*  offs_s = (float*) (smraw + OFF_OFFS);
    float*  lpi_s  = (float*) (smraw + OFF_LPI);
    float*  lpi2_s = (float*) (smraw + OFF_LPI2);
    float*  wbg_s  = (float*) (smraw + OFF_WBG);
    float*  phi_s  = (float*) (smraw + OFF_PHI);
    float*  scr    = (float*) (smraw + OFF_SCR);

    __shared__ float kl_s, c0_s;
    __shared__ double wsum[TPB / 32];

    const int tid = threadIdx.x, wid = tid >> 5, lane = tid & 31;
    const int g = lane >> 2, t4 = lane & 3;
    float* stg = (float*)(smraw + OFF_STG) + wid * (16 * 68);   // warp-private

    // ---------------- in-CTA precompute ----------------
    if (tid < 64) {
        float uu  = u_noise[tid];
        float gmb = -__logf(-__logf(uu + 1e-9f) + 1e-9f);
        float pl  = phi_logits[tid];
        float phi = 1.0f / (1.0f + __expf(-(pl + gmb)));
        phi_s[tid] = phi;
        float qphi = 1.0f / (1.0f + __expf(-pl));
        qphi = fminf(fmaxf(qphi, 1e-6f), 1.0f - 1e-6f);
        if (blockIdx.x == 0) out[1 + tid] = qphi;
        float p = fminf(fmaxf(prior_p[tid], 1e-6f), 1.0f - 1e-6f);
        scr[tid]       = qphi * (__logf(qphi) - __logf(p))
                       + (1.0f - qphi) * (__logf(1.0f - qphi) - __logf(1.0f - p));
        scr[64 + tid]  = (1.0f - phi) * (LOG2PI_F - 2.0f);
        scr[128 + tid] = pi_logits[tid];
        wbg_s[tid]     = (1.0f - phi) * EXP2_F;
    }
    __syncthreads();
    if (tid == 0) {
        float kl = 0.f, c0 = 0.f;
        #pragma unroll
        for (int i = 0; i < 64; i++) { kl += scr[i]; c0 += scr[64 + i]; }
        kl_s = kl; c0_s = c0;
    }
    if (tid < 64) {     // log(softmax(pi)+1e-9)
        float m = -3.4e38f;
        #pragma unroll
        for (int k = 0; k < 64; k++) m = fmaxf(m, scr[128 + k]);
        float ss = 0.f;
        #pragma unroll
        for (int k = 0; k < 64; k++) ss += __expf(scr[128 + k] - m);
        float lpi = __logf(__expf(scr[128 + tid] - m) / ss + 1e-9f);
        lpi_s[tid]  = lpi;
        lpi2_s[tid] = lpi * LOG2E_F;
    }

    // packed B fragments: entry e = (j*4 + ks)*32 + le
    for (int e = tid; e < 8 * 4 * 32; e += TPB) {
        int le = e & 31, ks = (e >> 5) & 3, j = e >> 7;
        int n = 8 * j + (le >> 2);
        int d0 = 16 * ks + 2 * (le & 3);
        float lin[4], aa[4];
        #pragma unroll
        for (int p = 0; p < 4; p++) {
            int d = d0 + (p & 1) + (p >> 1) * 8;        // d0, d0+1, d0+8, d0+9
            float lv = fminf(fmaxf(q_logvar[n * Dd + d], -5.0f), 5.0f);
            float a  = phi_s[d] * __expf(-lv);
            aa[p]  = a;
            lin[p] = -2.0f * q_mu[n * Dd + d] * a;
        }
        float4 v;
        *(uint32_t*)&v.x = f2h2(lin[0], lin[1]);
        *(uint32_t*)&v.y = f2h2(lin[2], lin[3]);
        *(uint32_t*)&v.z = f2h2(aa[0],  aa[1]);
        *(uint32_t*)&v.w = f2h2(aa[2],  aa[3]);
        B_s[e] = v;
    }
    __syncthreads();    // scr free; reuse for offs partials
    {
        int k = tid & 63, part = tid >> 6;
        float s = 0.f;
        #pragma unroll
        for (int d = part * 16; d < part * 16 + 16; d++) {
            float lv = fminf(fmaxf(q_logvar[k * Dd + d], -5.0f), 5.0f);
            float a  = phi_s[d] * __expf(-lv);
            float mu = q_mu[k * Dd + d];
            s += phi_s[d] * (LOG2PI_F + lv) + mu * mu * a;
        }
        scr[tid] = s;
    }
    __syncthreads();
    if (tid < 64)
        offs_s[tid] = -0.5f * (scr[tid] + scr[64 + tid] + scr[128 + tid] + scr[192 + tid]);
    __syncthreads();    // LAST block sync; shared tables read-only below

    const float C0 = c0_s;
    double lsesum = 0.0;

    // ---- steal first tile + preload its X fragments ----
    unsigned int tile;
    if (lane == 0) tile = atomicAdd(&g_tile, 1u);
    tile = __shfl_sync(0xffffffffu, tile, 0);
    float2 v[4][8];   // [ks][4 rows lo-cols, 4 rows hi-cols]
    if (tile < NCH) {
        const float2* Xg = (const float2*)X + (size_t)((int)tile * 32 + g) * 32 + t4;
        #pragma unroll
        for (int ks = 0; ks < 4; ks++) {
            v[ks][0] = Xg[8*ks];           v[ks][1] = Xg[256 + 8*ks];
            v[ks][2] = Xg[512 + 8*ks];     v[ks][3] = Xg[768 + 8*ks];
            v[ks][4] = Xg[8*ks + 4];       v[ks][5] = Xg[256 + 8*ks + 4];
            v[ks][6] = Xg[512 + 8*ks + 4]; v[ks][7] = Xg[768 + 8*ks + 4];
        }
    }

    // =================== pipelined work-stealing m32 loop ===================
    while (tile < NCH) {
        const int row0 = (int)tile * 32;

        // steal NEXT tile early (ATOMG latency hides under MMA)
        unsigned int nt;
        if (lane == 0) nt = atomicAdd(&g_tile, 1u);
        nt = __shfl_sync(0xffffffffu, nt, 0);

        float c[2][8][4];
        #pragma unroll
        for (int u = 0; u < 2; u++)
            #pragma unroll
            for (int j = 0; j < 8; j++)
                { c[u][j][0]=0.f; c[u][j][1]=0.f; c[u][j][2]=0.f; c[u][j][3]=0.f; }
        float bg[4] = {0.f, 0.f, 0.f, 0.f};

        #pragma unroll
        for (int ks = 0; ks < 4; ks++) {
            float2 v00 = v[ks][0], v01 = v[ks][1], v10 = v[ks][2], v11 = v[ks][3];
            float2 v02 = v[ks][4], v03 = v[ks][5], v12 = v[ks][6], v13 = v[ks][7];

            float2 w0 = *(const float2*)(wbg_s + 16 * ks + 2 * t4);
            float2 w1 = *(const float2*)(wbg_s + 16 * ks + 2 * t4 + 8);
            bg[0] = fmaf(w0.x, v00.x*v00.x, fmaf(w0.y, v00.y*v00.y,
                     fmaf(w1.x, v02.x*v02.x, fmaf(w1.y, v02.y*v02.y, bg[0]))));
            bg[1] = fmaf(w0.x, v01.x*v01.x, fmaf(w0.y, v01.y*v01.y,
                     fmaf(w1.x, v03.x*v03.x, fmaf(w1.y, v03.y*v03.y, bg[1]))));
            bg[2] = fmaf(w0.x, v10.x*v10.x, fmaf(w0.y, v10.y*v10.y,
                     fmaf(w1.x, v12.x*v12.x, fmaf(w1.y, v12.y*v12.y, bg[2]))));
            bg[3] = fmaf(w0.x, v11.x*v11.x, fmaf(w0.y, v11.y*v11.y,
                     fmaf(w1.x, v13.x*v13.x, fmaf(w1.y, v13.y*v13.y, bg[3]))));

            uint32_t A0[4] = { f2h2(v00.x,v00.y), f2h2(v01.x,v01.y),
                               f2h2(v02.x,v02.y), f2h2(v03.x,v03.y) };
            uint32_t A1[4] = { f2h2(v10.x,v10.y), f2h2(v11.x,v11.y),
                               f2h2(v12.x,v12.y), f2h2(v13.x,v13.y) };
            uint32_t Q0[4] = { h2sq(A0[0]), h2sq(A0[1]), h2sq(A0[2]), h2sq(A0[3]) };
            uint32_t Q1[4] = { h2sq(A1[0]), h2sq(A1[1]), h2sq(A1[2]), h2sq(A1[3]) };

            const float4* bp = B_s + ks * 32 + lane;
            #pragma unroll
            for (int j = 0; j < 8; j++) {
                float4 b = bp[j * 128];
                uint32_t bl0 = *(uint32_t*)&b.x, bl1 = *(uint32_t*)&b.y;
                uint32_t bq0 = *(uint32_t*)&b.z, bq1 = *(uint32_t*)&b.w;
                mma16(c[0][j], A0, bl0, bl1);
                mma16(c[0][j], Q0, bq0, bq1);
                mma16(c[1][j], A1, bl0, bl1);
                mma16(c[1][j], Q1, bq0, bq1);
            }
        }
        // v is dead: prefetch NEXT tile's X now; DRAM latency hides under epilogue
        if (nt < NCH) {
            const float2* Xg = (const float2*)X + (size_t)((int)nt * 32 + g) * 32 + t4;
            #pragma unroll
            for (int ks = 0; ks < 4; ks++) {
                v[ks][0] = Xg[8*ks];           v[ks][1] = Xg[256 + 8*ks];
                v[ks][2] = Xg[512 + 8*ks];     v[ks][3] = Xg[768 + 8*ks];
                v[ks][4] = Xg[8*ks + 4];       v[ks][5] = Xg[256 + 8*ks + 4];
                v[ks][6] = Xg[512 + 8*ks + 4]; v[ks][7] = Xg[768 + 8*ks + 4];
            }
        }

        bg[0] += __shfl_xor_sync(0xffffffffu, bg[0], 1);
        bg[0] += __shfl_xor_sync(0xffffffffu, bg[0], 2);
        bg[1] += __shfl_xor_sync(0xffffffffu, bg[1], 1);
        bg[1] += __shfl_xor_sync(0xffffffffu, bg[1], 2);
        bg[2] += __shfl_xor_sync(0xffffffffu, bg[2], 1);
        bg[2] += __shfl_xor_sync(0xffffffffu, bg[2], 2);
        bg[3] += __shfl_xor_sync(0xffffffffu, bg[3], 1);
        bg[3] += __shfl_xor_sync(0xffffffffu, bg[3], 2);

        // ---- epilogue per m16 tile: lse + stage + coalesced copy-out ----
        #pragma unroll
        for (int u = 0; u < 2; u++) {
            #pragma unroll
            for (int h = 0; h < 2; h++) {
                float lpbg = -0.5f * (C0 + bg[2 * u + h]);
                float lp[16];
                float mx = -3.4e38f;
                #pragma unroll
                for (int j = 0; j < 8; j++) {
                    int col = 8 * j + 2 * t4;
                    float v0 = fmaf(-0.5f, c[u][j][2*h],   offs_s[col])   + lpbg;
                    float v1 = fmaf(-0.5f, c[u][j][2*h+1], offs_s[col+1]) + lpbg;
                    lp[2*j] = v0; lp[2*j+1] = v1;
                    mx = fmaxf(mx, fmaxf(v0 + lpi_s[col], v1 + lpi_s[col+1]));
                }
                mx = fmaxf(mx, __shfl_xor_sync(0xffffffffu, mx, 1));
                mx = fmaxf(mx, __shfl_xor_sync(0xffffffffu, mx, 2));

                // exp args rebuilt from lp via lpi2 table (no y[] registers)
                float mxl = mx * LOG2E_F;
                int cb = 2 * t4;
                __half2 e0 = ex2_h2(fmaf(lp[0],  LOG2E_F, lpi2_s[cb]      - mxl),
                                    fmaf(lp[1],  LOG2E_F, lpi2_s[cb + 1]  - mxl));
                __half2 e1 = ex2_h2(fmaf(lp[2],  LOG2E_F, lpi2_s[cb + 8]  - mxl),
                                    fmaf(lp[3],  LOG2E_F, lpi2_s[cb + 9]  - mxl));
                __half2 e2 = ex2_h2(fmaf(lp[4],  LOG2E_F, lpi2_s[cb + 16] - mxl),
                                    fmaf(lp[5],  LOG2E_F, lpi2_s[cb + 17] - mxl));
                __half2 e3 = ex2_h2(fmaf(lp[6],  LOG2E_F, lpi2_s[cb + 24] - mxl),
                                    fmaf(lp[7],  LOG2E_F, lpi2_s[cb + 25] - mxl));
                __half2 e4 = ex2_h2(fmaf(lp[8],  LOG2E_F, lpi2_s[cb + 32] - mxl),
                                    fmaf(lp[9],  LOG2E_F, lpi2_s[cb + 33] - mxl));
                __half2 e5 = ex2_h2(fmaf(lp[10], LOG2E_F, lpi2_s[cb + 40] - mxl),
                                    fmaf(lp[11], LOG2E_F, lpi2_s[cb + 41] - mxl));
                __half2 e6 = ex2_h2(fmaf(lp[12], LOG2E_F, lpi2_s[cb + 48] - mxl),
                                    fmaf(lp[13], LOG2E_F, lpi2_s[cb + 49] - mxl));
                __half2 e7 = ex2_h2(fmaf(lp[14], LOG2E_F, lpi2_s[cb + 56] - mxl),
                                    fmaf(lp[15], LOG2E_F, lpi2_s[cb + 57] - mxl));
                __half2 s01 = __hadd2(e0, e1), s23 = __hadd2(e2, e3);
                __half2 s45 = __hadd2(e4, e5), s67 = __hadd2(e6, e7);
                float2 f0 = __half22float2(s01), f1 = __half22float2(s23);
                float2 f2 = __half22float2(s45), f3 = __half22float2(s67);
                float se = (f0.x + f0.y) + (f1.x + f1.y)
                         + (f2.x + f2.y) + (f3.x + f3.y);
                se += __shfl_xor_sync(0xffffffffu, se, 1);
                se += __shfl_xor_sync(0xffffffffu, se, 2);
                if (t4 == 0) lsesum += (double)(mx + __logf(se));

                // stage lp (padded stride 68; STS.64 8B-aligned)
                float* srow = stg + (8 * h + g) * 68 + 2 * t4;
                #pragma unroll
                for (int j = 0; j < 8; j++)
                    *(float2*)(srow + 8 * j) = make_float2(lp[2*j], lp[2*j+1]);
            }
            __syncwarp();
            // coalesced copy-out of 16 rows; out+65 is 4B-aligned -> STG.32
            float* ob = out + 65 + (size_t)(row0 + 16 * u) * Kk;
            #pragma unroll
            for (int i = 0; i < 32; i++) {
                int idx = i * 32 + lane;
                ob[idx] = stg[(idx >> 6) * 68 + (idx & 63)];
            }
            __syncwarp();
        }
        tile = nt;
    }

    // ---- loss reduce + last-CTA finalize (deterministic replay reset) ----
    #pragma unroll
    for (int s = 16; s; s >>= 1)
        lsesum += __shfl_xor_sync(0xffffffffu, lsesum, s);
    if (lane == 0) wsum[wid] = lsesum;
    __syncthreads();
    if (tid == 0) {
        double bsum = 0.0;
        #pragma unroll
        for (int w = 0; w < TPB / 32; w++) bsum += wsum[w];
        atomicAdd(&g_lse, bsum);
        __threadfence();
        unsigned int old = atomicAdd(&g_count, 1u);
        if (old == GRID - 1) {
            __threadfence();
            double total = atomicAdd(&g_lse, 0.0);
            out[0] = (float)((double)kl_s * (double)Nn - total);
            g_lse   = 0.0;
            g_tile  = 0u;
            g_count = 0u;
        }
    }
}

// ---------------------------------------------------------------------------
extern "C" void kernel_launch(void* const* d_in, const int* in_sizes, int n_in,
                              void* d_out, int out_size)
{
    const float* X  = (const float*)d_in[0];
    const float* u  = (const float*)d_in[1];
    const float* pl = (const float*)d_in[2];
    const float* mu = (const float*)d_in[3];
    const float* lv = (const float*)d_in[4];
    const float* pi = (const float*)d_in[5];
    const float* pp = (const float*)d_in[6];
    float* out = (float*)d_out;

    cudaFuncSetAttribute(gmm_kernel,
                         cudaFuncAttributeMaxDynamicSharedMemorySize, SMEM_BYTES);

    gmm_kernel<<<GRID, TPB, SMEM_BYTES>>>(X, u, pl, mu, lv, pi, pp, out);
}

// round 15
// speedup vs baseline: 1.1175x; 1.1175x over previous
#include <cuda_runtime.h>
#include <cuda_fp16.h>
#include <math.h>
#include <stdint.h>

// ---------------- problem constants ----------------
#define Nn 262144
#define Dd 64
#define Kk 64
#define TPB 256
#define GRID 296                 // persistent CTAs (2/SM x 148)
#define NCH (Nn/32)              // 8192 m32 chunks
#define LOG2PI_F 1.83787706640934548356f
#define EXP2_F 7.389056098930650f     // exp(2) = exp(-prior_logvar_0)
#define LOG2E_F 1.44269504088896340736f

// ---------------- smem layout (bytes, dynamic) ----------------
#define OFF_B     0               // 9*4*32 float4 = 18432
#define OFF_STG   18432           // 8 warps * 16*68 floats = 34816
#define OFF_OFFS  53248           // 64 f32
#define OFF_LPI   53504
#define OFF_PHI   53760
#define OFF_SCR   54016           // 256 f32
#define SMEM_BYTES 55040

// ---------------- device globals ----------------
__device__ double g_lse;
__device__ unsigned int g_count;
__device__ unsigned int g_tile;

__device__ __forceinline__ void mma16(float c[4], const uint32_t a[4],
                                      uint32_t b0, uint32_t b1) {
    asm volatile("mma.sync.aligned.m16n8k16.row.col.f32.f16.f16.f32 "
        "{%0,%1,%2,%3},{%4,%5,%6,%7},{%8,%9},{%0,%1,%2,%3};"
        : "+f"(c[0]), "+f"(c[1]), "+f"(c[2]), "+f"(c[3])
        : "r"(a[0]), "r"(a[1]), "r"(a[2]), "r"(a[3]), "r"(b0), "r"(b1));
}
__device__ __forceinline__ uint32_t h2sq(uint32_t a) {
    __half2 h = *reinterpret_cast<__half2*>(&a);
    __half2 q = __hmul2(h, h);
    return *reinterpret_cast<uint32_t*>(&q);
}
__device__ __forceinline__ uint32_t f2h2(float lo, float hi) {
    __half2 h = __floats2half2_rn(lo, hi);
    return *reinterpret_cast<uint32_t*>(&h);
}
__device__ __forceinline__ __half2 ex2_h2(float z0, float z1) {
    __half2 z = __floats2half2_rn(z0, z1);
    uint32_t zi = *reinterpret_cast<uint32_t*>(&z), r;
    asm("ex2.approx.f16x2 %0, %1;" : "=r"(r) : "r"(zi));
    return *reinterpret_cast<__half2*>(&r);
}

// ---------------------------------------------------------------------------
__global__ void __launch_bounds__(TPB, 2)
gmm_kernel(const float* __restrict__ X,
           const float* __restrict__ u_noise,
           const float* __restrict__ phi_logits,
           const float* __restrict__ q_mu,
           const float* __restrict__ q_logvar,
           const float* __restrict__ pi_logits,
           const float* __restrict__ prior_p,
           float* __restrict__ out)
{
    extern __shared__ char smraw[];
    float4* B_s    = (float4*)(smraw + OFF_B);
    float*  offs_s = (float*) (smraw + OFF_OFFS);
    float*  lpi_s  = (float*) (smraw + OFF_LPI);
    float*  phi_s  = (float*) (smraw + OFF_PHI);
    float*  scr    = (float*) (smraw + OFF_SCR);

    __shared__ float kl_s, c0_s;
    __shared__ double wsum[TPB / 32];

    const int tid = threadIdx.x, wid = tid >> 5, lane = tid & 31;
    const int g = lane >> 2, t4 = lane & 3;
    float* stg = (float*)(smraw + OFF_STG) + wid * (16 * 68);   // warp-private

    // ---------------- in-CTA precompute ----------------
    if (tid < 64) {
        float uu  = u_noise[tid];
        float gmb = -__logf(-__logf(uu + 1e-9f) + 1e-9f);
        float pl  = phi_logits[tid];
        float phi = 1.0f / (1.0f + __expf(-(pl + gmb)));
        phi_s[tid] = phi;
        float qphi = 1.0f / (1.0f + __expf(-pl));
        qphi = fminf(fmaxf(qphi, 1e-6f), 1.0f - 1e-6f);
        if (blockIdx.x == 0) out[1 + tid] = qphi;
        float p = fminf(fmaxf(prior_p[tid], 1e-6f), 1.0f - 1e-6f);
        scr[tid]       = qphi * (__logf(qphi) - __logf(p))
                       + (1.0f - qphi) * (__logf(1.0f - qphi) - __logf(1.0f - p));
        scr[64 + tid]  = (1.0f - phi) * (LOG2PI_F - 2.0f);
        scr[128 + tid] = pi_logits[tid];
    }
    __syncthreads();
    if (tid == 0) {
        float kl = 0.f, c0 = 0.f;
        #pragma unroll
        for (int i = 0; i < 64; i++) { kl += scr[i]; c0 += scr[64 + i]; }
        kl_s = kl; c0_s = c0;
    }
    if (tid < 64) {     // log(softmax(pi)+1e-9)
        float m = -3.4e38f;
        #pragma unroll
        for (int k = 0; k < 64; k++) m = fmaxf(m, scr[128 + k]);
        float ss = 0.f;
        #pragma unroll
        for (int k = 0; k < 64; k++) ss += __expf(scr[128 + k] - m);
        lpi_s[tid] = __logf(__expf(scr[128 + tid] - m) / ss + 1e-9f);
    }

    // packed B fragments (9 n-tiles; n=64 column = background quad weights):
    // entry e = (j*4 + ks)*32 + le
    for (int e = tid; e < 9 * 4 * 32; e += TPB) {
        int le = e & 31, ks = (e >> 5) & 3, j = e >> 7;
        int n = 8 * j + (le >> 2);
        int d0 = 16 * ks + 2 * (le & 3);
        float lin[4] = {0.f, 0.f, 0.f, 0.f}, qd[4] = {0.f, 0.f, 0.f, 0.f};
        if (n < Kk) {
            #pragma unroll
            for (int p = 0; p < 4; p++) {
                int d = d0 + (p & 1) + (p >> 1) * 8;    // d0, d0+1, d0+8, d0+9
                float lv = fminf(fmaxf(q_logvar[n * Dd + d], -5.0f), 5.0f);
                float a  = phi_s[d] * __expf(-lv);
                qd[p]  = a;
                lin[p] = -2.0f * q_mu[n * Dd + d] * a;
            }
        } else if (n == Kk) {
            #pragma unroll
            for (int p = 0; p < 4; p++) {
                int d = d0 + (p & 1) + (p >> 1) * 8;
                qd[p] = (1.0f - phi_s[d]) * EXP2_F;     // bg quad weights
            }
        }
        float4 v;
        *(uint32_t*)&v.x = f2h2(lin[0], lin[1]);
        *(uint32_t*)&v.y = f2h2(lin[2], lin[3]);
        *(uint32_t*)&v.z = f2h2(qd[0],  qd[1]);
        *(uint32_t*)&v.w = f2h2(qd[2],  qd[3]);
        B_s[e] = v;
    }
    __syncthreads();    // scr free; reuse for offs partials
    {
        int k = tid & 63, part = tid >> 6;
        float s = 0.f;
        #pragma unroll
        for (int d = part * 16; d < part * 16 + 16; d++) {
            float lv = fminf(fmaxf(q_logvar[k * Dd + d], -5.0f), 5.0f);
            float a  = phi_s[d] * __expf(-lv);
            float mu = q_mu[k * Dd + d];
            s += phi_s[d] * (LOG2PI_F + lv) + mu * mu * a;
        }
        scr[tid] = s;
    }
    __syncthreads();
    if (tid < 64)
        offs_s[tid] = -0.5f * (scr[tid] + scr[64 + tid] + scr[128 + tid] + scr[192 + tid]);
    __syncthreads();    // LAST block sync; shared tables read-only below

    const float C0 = c0_s;
    double lsesum = 0.0;

    // =================== work-stealing per-warp m32 chunk loop ===================
    for (;;) {
        unsigned int tile;
        if (lane == 0) tile = atomicAdd(&g_tile, 1u);
        tile = __shfl_sync(0xffffffffu, tile, 0);
        if (tile >= NCH) break;
        const int row0 = (int)tile * 32;
        const float2* Xg = (const float2*)X + (size_t)(row0 + g) * 32 + t4;

        float c[2][9][4];
        #pragma unroll
        for (int u = 0; u < 2; u++)
            #pragma unroll
            for (int j = 0; j < 9; j++)
                { c[u][j][0]=0.f; c[u][j][1]=0.f; c[u][j][2]=0.f; c[u][j][3]=0.f; }

        #pragma unroll
        for (int ks = 0; ks < 4; ks++) {
            // tile0: rows g, g+8 ; tile1: rows g+16, g+24 (row stride = 32 float2)
            float2 v00 = Xg[8 * ks],           v01 = Xg[256 + 8 * ks];
            float2 v02 = Xg[8 * ks + 4],       v03 = Xg[256 + 8 * ks + 4];
            float2 v10 = Xg[512 + 8 * ks],     v11 = Xg[768 + 8 * ks];
            float2 v12 = Xg[512 + 8 * ks + 4], v13 = Xg[768 + 8 * ks + 4];

            uint32_t A0[4] = { f2h2(v00.x,v00.y), f2h2(v01.x,v01.y),
                               f2h2(v02.x,v02.y), f2h2(v03.x,v03.y) };
            uint32_t A1[4] = { f2h2(v10.x,v10.y), f2h2(v11.x,v11.y),
                               f2h2(v12.x,v12.y), f2h2(v13.x,v13.y) };
            uint32_t Q0[4] = { h2sq(A0[0]), h2sq(A0[1]), h2sq(A0[2]), h2sq(A0[3]) };
            uint32_t Q1[4] = { h2sq(A1[0]), h2sq(A1[1]), h2sq(A1[2]), h2sq(A1[3]) };

            const float4* bp = B_s + ks * 32 + lane;
            #pragma unroll
            for (int j = 0; j < 9; j++) {
                float4 b = bp[j * 128];               // one LDS.128, reused 4x
                uint32_t bl0 = *(uint32_t*)&b.x, bl1 = *(uint32_t*)&b.y;
                uint32_t bq0 = *(uint32_t*)&b.z, bq1 = *(uint32_t*)&b.w;
                mma16(c[0][j], A0, bl0, bl1);
                mma16(c[0][j], Q0, bq0, bq1);
                mma16(c[1][j], A1, bl0, bl1);
                mma16(c[1][j], Q1, bq0, bq1);
            }
        }

        // ---- epilogue per m16 tile: lse + stage + coalesced copy-out ----
        #pragma unroll
        for (int u = 0; u < 2; u++) {
            #pragma unroll
            for (int h = 0; h < 2; h++) {
                float bgq  = __shfl_sync(0xffffffffu, c[u][8][2 * h], lane & ~3);
                float lpbg = -0.5f * (C0 + bgq);
                float lp[16];
                float mx = -3.4e38f;
                #pragma unroll
                for (int j = 0; j < 8; j++) {
                    int col = 8 * j + 2 * t4;
                    float v0 = fmaf(-0.5f, c[u][j][2*h],   offs_s[col])   + lpbg;
                    float v1 = fmaf(-0.5f, c[u][j][2*h+1], offs_s[col+1]) + lpbg;
                    lp[2*j] = v0; lp[2*j+1] = v1;
                    mx = fmaxf(mx, fmaxf(v0 + lpi_s[col], v1 + lpi_s[col+1]));
                }
                mx = fmaxf(mx, __shfl_xor_sync(0xffffffffu, mx, 1));
                mx = fmaxf(mx, __shfl_xor_sync(0xffffffffu, mx, 2));

                float mxl = mx * LOG2E_F;
                int cb = 2 * t4;
                __half2 e0 = ex2_h2(fmaf(lp[0]  + lpi_s[cb],      LOG2E_F, -mxl),
                                    fmaf(lp[1]  + lpi_s[cb + 1],  LOG2E_F, -mxl));
                __half2 e1 = ex2_h2(fmaf(lp[2]  + lpi_s[cb + 8],  LOG2E_F, -mxl),
                                    fmaf(lp[3]  + lpi_s[cb + 9],  LOG2E_F, -mxl));
                __half2 e2 = ex2_h2(fmaf(lp[4]  + lpi_s[cb + 16], LOG2E_F, -mxl),
                                    fmaf(lp[5]  + lpi_s[cb + 17], LOG2E_F, -mxl));
                __half2 e3 = ex2_h2(fmaf(lp[6]  + lpi_s[cb + 24], LOG2E_F, -mxl),
                                    fmaf(lp[7]  + lpi_s[cb + 25], LOG2E_F, -mxl));
                __half2 e4 = ex2_h2(fmaf(lp[8]  + lpi_s[cb + 32], LOG2E_F, -mxl),
                                    fmaf(lp[9]  + lpi_s[cb + 33], LOG2E_F, -mxl));
                __half2 e5 = ex2_h2(fmaf(lp[10] + lpi_s[cb + 40], LOG2E_F, -mxl),
                                    fmaf(lp[11] + lpi_s[cb + 41], LOG2E_F, -mxl));
                __half2 e6 = ex2_h2(fmaf(lp[12] + lpi_s[cb + 48], LOG2E_F, -mxl),
                                    fmaf(lp[13] + lpi_s[cb + 49], LOG2E_F, -mxl));
                __half2 e7 = ex2_h2(fmaf(lp[14] + lpi_s[cb + 56], LOG2E_F, -mxl),
                                    fmaf(lp[15] + lpi_s[cb + 57], LOG2E_F, -mxl));
                __half2 s01 = __hadd2(e0, e1), s23 = __hadd2(e2, e3);
                __half2 s45 = __hadd2(e4, e5), s67 = __hadd2(e6, e7);
                float2 f0 = __half22float2(s01), f1 = __half22float2(s23);
                float2 f2 = __half22float2(s45), f3 = __half22float2(s67);
                float se = (f0.x + f0.y) + (f1.x + f1.y)
                         + (f2.x + f2.y) + (f3.x + f3.y);
                se += __shfl_xor_sync(0xffffffffu, se, 1);
                se += __shfl_xor_sync(0xffffffffu, se, 2);
                if (t4 == 0) lsesum += (double)(mx + __logf(se));

                // stage lp (padded stride 68; STS.64 8B-aligned, conflict-free)
                float* srow = stg + (8 * h + g) * 68 + 2 * t4;
                #pragma unroll
                for (int j = 0; j < 8; j++)
                    *(float2*)(srow + 8 * j) = make_float2(lp[2*j], lp[2*j+1]);
            }
            __syncwarp();
            // coalesced copy-out of 16 rows; out+65 is 4B-aligned -> STG.32
            float* ob = out + 65 + (size_t)(row0 + 16 * u) * Kk;
            #pragma unroll
            for (int i = 0; i < 32; i++) {
                int idx = i * 32 + lane;
                ob[idx] = stg[(idx >> 6) * 68 + (idx & 63)];
            }
            __syncwarp();
        }
    }

    // ---- loss reduce + last-CTA finalize (deterministic replay reset) ----
    #pragma unroll
    for (int s = 16; s; s >>= 1)
        lsesum += __shfl_xor_sync(0xffffffffu, lsesum, s);
    if (lane == 0) wsum[wid] = lsesum;
    __syncthreads();
    if (tid == 0) {
        double bsum = 0.0;
        #pragma unroll
        for (int w = 0; w < TPB / 32; w++) bsum += wsum[w];
        atomicAdd(&g_lse, bsum);
        __threadfence();
        unsigned int old = atomicAdd(&g_count, 1u);
        if (old == GRID - 1) {
            __threadfence();
            double total = atomicAdd(&g_lse, 0.0);
            out[0] = (float)((double)kl_s * (double)Nn - total);
            g_lse   = 0.0;
            g_tile  = 0u;
            g_count = 0u;
        }
    }
}

// ---------------------------------------------------------------------------
extern "C" void kernel_launch(void* const* d_in, const int* in_sizes, int n_in,
                              void* d_out, int out_size)
{
    const float* X  = (const float*)d_in[0];
    const float* u  = (const float*)d_in[1];
    const float* pl = (const float*)d_in[2];
    const float* mu = (const float*)d_in[3];
    const float* lv = (const float*)d_in[4];
    const float* pi = (const float*)d_in[5];
    const float* pp = (const float*)d_in[6];
    float* out = (float*)d_out;

    cudaFuncSetAttribute(gmm_kernel,
                         cudaFuncAttributeMaxDynamicSharedMemorySize, SMEM_BYTES);

    gmm_kernel<<<GRID, TPB, SMEM_BYTES>>>(X, u, pl, mu, lv, pi, pp, out);
}

// round 16
// speedup vs baseline: 1.1643x; 1.0419x over previous
#include <cuda_runtime.h>
#include <cuda_fp16.h>
#include <math.h>
#include <stdint.h>

// ---------------- problem constants ----------------
#define Nn 262144
#define Dd 64
#define Kk 64
#define TPB 256
#define GRID 296                 // persistent CTAs (2/SM x 148)
#define NCH (Nn/32)              // 8192 m32 chunks
#define LOG2PI_F 1.83787706640934548356f
#define EXP2_F 7.389056098930650f     // exp(2) = exp(-prior_logvar_0)
#define LOG2E_F 1.44269504088896340736f
#define LN2_F   0.69314718055994530942f
#define M05L_F  (-0.5f * LOG2E_F)

// ---------------- smem layout (bytes, dynamic) ----------------
#define OFF_B     0               // 9*4*32 float4 = 18432
#define OFF_STG   18432           // 8 warps * 16*68 floats = 34816
#define OFF_OFFS  53248           // 64 f32 (natural offs, for nothing but build)
#define OFF_LPI   53504           // 64 f32 log(pi)+...
#define OFF_OFF2  53760           // 64 f32 (offs+lpi)*log2e
#define OFF_PHI   54016
#define OFF_SCR   54272           // 256 f32
#define SMEM_BYTES 55296

// ---------------- device globals ----------------
__device__ double g_lse;
__device__ unsigned int g_count;
__device__ unsigned int g_tile;

__device__ __forceinline__ void mma16(float c[4], const uint32_t a[4],
                                      uint32_t b0, uint32_t b1) {
    asm volatile("mma.sync.aligned.m16n8k16.row.col.f32.f16.f16.f32 "
        "{%0,%1,%2,%3},{%4,%5,%6,%7},{%8,%9},{%0,%1,%2,%3};"
        : "+f"(c[0]), "+f"(c[1]), "+f"(c[2]), "+f"(c[3])
        : "r"(a[0]), "r"(a[1]), "r"(a[2]), "r"(a[3]), "r"(b0), "r"(b1));
}
__device__ __forceinline__ uint32_t h2sq(uint32_t a) {
    __half2 h = *reinterpret_cast<__half2*>(&a);
    __half2 q = __hmul2(h, h);
    return *reinterpret_cast<uint32_t*>(&q);
}
__device__ __forceinline__ uint32_t f2h2(float lo, float hi) {
    __half2 h = __floats2half2_rn(lo, hi);
    return *reinterpret_cast<uint32_t*>(&h);
}
__device__ __forceinline__ __half2 ex2_h2(float z0, float z1) {
    __half2 z = __floats2half2_rn(z0, z1);
    uint32_t zi = *reinterpret_cast<uint32_t*>(&z), r;
    asm("ex2.approx.f16x2 %0, %1;" : "=r"(r) : "r"(zi));
    return *reinterpret_cast<__half2*>(&r);
}

// ---------------------------------------------------------------------------
__global__ void __launch_bounds__(TPB, 2)
gmm_kernel(const float* __restrict__ X,
           const float* __restrict__ u_noise,
           const float* __restrict__ phi_logits,
           const float* __restrict__ q_mu,
           const float* __restrict__ q_logvar,
           const float* __restrict__ pi_logits,
           const float* __restrict__ prior_p,
           float* __restrict__ out)
{
    extern __shared__ char smraw[];
    float4* B_s    = (float4*)(smraw + OFF_B);
    float*  offs_s = (float*) (smraw + OFF_OFFS);
    float*  lpi_s  = (float*) (smraw + OFF_LPI);
    float*  off2_s = (float*) (smraw + OFF_OFF2);
    float*  phi_s  = (float*) (smraw + OFF_PHI);
    float*  scr    = (float*) (smraw + OFF_SCR);

    __shared__ float kl_s, c0_s;
    __shared__ double wsum[TPB / 32];

    const int tid = threadIdx.x, wid = tid >> 5, lane = tid & 31;
    const int g = lane >> 2, t4 = lane & 3;
    float* stg = (float*)(smraw + OFF_STG) + wid * (16 * 68);   // warp-private

    // ---------------- in-CTA precompute ----------------
    if (tid < 64) {
        float uu  = u_noise[tid];
        float gmb = -__logf(-__logf(uu + 1e-9f) + 1e-9f);
        float pl  = phi_logits[tid];
        float phi = 1.0f / (1.0f + __expf(-(pl + gmb)));
        phi_s[tid] = phi;
        float qphi = 1.0f / (1.0f + __expf(-pl));
        qphi = fminf(fmaxf(qphi, 1e-6f), 1.0f - 1e-6f);
        if (blockIdx.x == 0) out[1 + tid] = qphi;
        float p = fminf(fmaxf(prior_p[tid], 1e-6f), 1.0f - 1e-6f);
        scr[tid]       = qphi * (__logf(qphi) - __logf(p))
                       + (1.0f - qphi) * (__logf(1.0f - qphi) - __logf(1.0f - p));
        scr[64 + tid]  = (1.0f - phi) * (LOG2PI_F - 2.0f);
        scr[128 + tid] = pi_logits[tid];
    }
    __syncthreads();
    if (tid == 0) {
        float kl = 0.f, c0 = 0.f;
        #pragma unroll
        for (int i = 0; i < 64; i++) { kl += scr[i]; c0 += scr[64 + i]; }
        kl_s = kl; c0_s = c0;
    }
    if (tid < 64) {     // log(softmax(pi)+1e-9)
        float m = -3.4e38f;
        #pragma unroll
        for (int k = 0; k < 64; k++) m = fmaxf(m, scr[128 + k]);
        float ss = 0.f;
        #pragma unroll
        for (int k = 0; k < 64; k++) ss += __expf(scr[128 + k] - m);
        lpi_s[tid] = __logf(__expf(scr[128 + tid] - m) / ss + 1e-9f);
    }

    // packed B fragments (9 n-tiles; n=64 column = background quad weights)
    for (int e = tid; e < 9 * 4 * 32; e += TPB) {
        int le = e & 31, ks = (e >> 5) & 3, j = e >> 7;
        int n = 8 * j + (le >> 2);
        int d0 = 16 * ks + 2 * (le & 3);
        float lin[4] = {0.f, 0.f, 0.f, 0.f}, qd[4] = {0.f, 0.f, 0.f, 0.f};
        if (n < Kk) {
            #pragma unroll
            for (int p = 0; p < 4; p++) {
                int d = d0 + (p & 1) + (p >> 1) * 8;    // d0, d0+1, d0+8, d0+9
                float lv = fminf(fmaxf(q_logvar[n * Dd + d], -5.0f), 5.0f);
                float a  = phi_s[d] * __expf(-lv);
                qd[p]  = a;
                lin[p] = -2.0f * q_mu[n * Dd + d] * a;
            }
        } else if (n == Kk) {
            #pragma unroll
            for (int p = 0; p < 4; p++) {
                int d = d0 + (p & 1) + (p >> 1) * 8;
                qd[p] = (1.0f - phi_s[d]) * EXP2_F;     // bg quad weights
            }
        }
        float4 v;
        *(uint32_t*)&v.x = f2h2(lin[0], lin[1]);
        *(uint32_t*)&v.y = f2h2(lin[2], lin[3]);
        *(uint32_t*)&v.z = f2h2(qd[0],  qd[1]);
        *(uint32_t*)&v.w = f2h2(qd[2],  qd[3]);
        B_s[e] = v;
    }
    __syncthreads();    // scr free; reuse for offs partials
    {
        int k = tid & 63, part = tid >> 6;
        float s = 0.f;
        #pragma unroll
        for (int d = part * 16; d < part * 16 + 16; d++) {
            float lv = fminf(fmaxf(q_logvar[k * Dd + d], -5.0f), 5.0f);
            float a  = phi_s[d] * __expf(-lv);
            float mu = q_mu[k * Dd + d];
            s += phi_s[d] * (LOG2PI_F + lv) + mu * mu * a;
        }
        scr[tid] = s;
    }
    __syncthreads();
    if (tid < 64) {
        float of = -0.5f * (scr[tid] + scr[64 + tid] + scr[128 + tid] + scr[192 + tid]);
        offs_s[tid] = of;
        off2_s[tid] = (of + lpi_s[tid]) * LOG2E_F;     // log2-domain table
    }
    __syncthreads();    // LAST block sync; shared tables read-only below

    const float C0 = c0_s;
    double lsesum = 0.0;

    // =================== work-stealing per-warp m32 chunk loop ===================
    for (;;) {
        unsigned int tile;
        if (lane == 0) tile = atomicAdd(&g_tile, 1u);
        tile = __shfl_sync(0xffffffffu, tile, 0);
        if (tile >= NCH) break;
        const int row0 = (int)tile * 32;
        const float2* Xg = (const float2*)X + (size_t)(row0 + g) * 32 + t4;

        float c[2][9][4];
        #pragma unroll
        for (int u = 0; u < 2; u++)
            #pragma unroll
            for (int j = 0; j < 9; j++)
                { c[u][j][0]=0.f; c[u][j][1]=0.f; c[u][j][2]=0.f; c[u][j][3]=0.f; }

        #pragma unroll
        for (int ks = 0; ks < 4; ks++) {
            // streaming loads: X is touched exactly once globally
            float2 v00 = __ldcs(Xg + 8 * ks);           float2 v01 = __ldcs(Xg + 256 + 8 * ks);
            float2 v02 = __ldcs(Xg + 8 * ks + 4);       float2 v03 = __ldcs(Xg + 256 + 8 * ks + 4);
            float2 v10 = __ldcs(Xg + 512 + 8 * ks);     float2 v11 = __ldcs(Xg + 768 + 8 * ks);
            float2 v12 = __ldcs(Xg + 512 + 8 * ks + 4); float2 v13 = __ldcs(Xg + 768 + 8 * ks + 4);

            uint32_t A0[4] = { f2h2(v00.x,v00.y), f2h2(v01.x,v01.y),
                               f2h2(v02.x,v02.y), f2h2(v03.x,v03.y) };
            uint32_t A1[4] = { f2h2(v10.x,v10.y), f2h2(v11.x,v11.y),
                               f2h2(v12.x,v12.y), f2h2(v13.x,v13.y) };
            uint32_t Q0[4] = { h2sq(A0[0]), h2sq(A0[1]), h2sq(A0[2]), h2sq(A0[3]) };
            uint32_t Q1[4] = { h2sq(A1[0]), h2sq(A1[1]), h2sq(A1[2]), h2sq(A1[3]) };

            const float4* bp = B_s + ks * 32 + lane;
            #pragma unroll
            for (int j = 0; j < 9; j++) {
                float4 b = bp[j * 128];               // one LDS.128, reused 4x
                uint32_t bl0 = *(uint32_t*)&b.x, bl1 = *(uint32_t*)&b.y;
                uint32_t bq0 = *(uint32_t*)&b.z, bq1 = *(uint32_t*)&b.w;
                mma16(c[0][j], A0, bl0, bl1);
                mma16(c[0][j], Q0, bq0, bq1);
                mma16(c[1][j], A1, bl0, bl1);
                mma16(c[1][j], Q1, bq0, bq1);
            }
        }

        // ---- epilogue per m16 tile (log2 domain): lse + stage + copy-out ----
        #pragma unroll
        for (int u = 0; u < 2; u++) {
            #pragma unroll
            for (int h = 0; h < 2; h++) {
                float bgq   = __shfl_sync(0xffffffffu, c[u][8][2 * h], lane & ~3);
                float lpbg2 = M05L_F * (C0 + bgq);     // log2-domain bg offset
                float y2[16];
                float mx2 = -3.4e38f;
                #pragma unroll
                for (int j = 0; j < 8; j++) {
                    int col = 8 * j + 2 * t4;
                    float a0 = fmaf(M05L_F, c[u][j][2*h],   off2_s[col])   + lpbg2;
                    float a1 = fmaf(M05L_F, c[u][j][2*h+1], off2_s[col+1]) + lpbg2;
                    y2[2*j] = a0; y2[2*j+1] = a1;
                    mx2 = fmaxf(mx2, fmaxf(a0, a1));
                }
                mx2 = fmaxf(mx2, __shfl_xor_sync(0xffffffffu, mx2, 1));
                mx2 = fmaxf(mx2, __shfl_xor_sync(0xffffffffu, mx2, 2));

                __half2 e0 = ex2_h2(y2[0]  - mx2, y2[1]  - mx2);
                __half2 e1 = ex2_h2(y2[2]  - mx2, y2[3]  - mx2);
                __half2 e2 = ex2_h2(y2[4]  - mx2, y2[5]  - mx2);
                __half2 e3 = ex2_h2(y2[6]  - mx2, y2[7]  - mx2);
                __half2 e4 = ex2_h2(y2[8]  - mx2, y2[9]  - mx2);
                __half2 e5 = ex2_h2(y2[10] - mx2, y2[11] - mx2);
                __half2 e6 = ex2_h2(y2[12] - mx2, y2[13] - mx2);
                __half2 e7 = ex2_h2(y2[14] - mx2, y2[15] - mx2);
                __half2 s01 = __hadd2(e0, e1), s23 = __hadd2(e2, e3);
                __half2 s45 = __hadd2(e4, e5), s67 = __hadd2(e6, e7);
                float2 f0 = __half22float2(s01), f1 = __half22float2(s23);
                float2 f2 = __half22float2(s45), f3 = __half22float2(s67);
                float se = (f0.x + f0.y) + (f1.x + f1.y)
                         + (f2.x + f2.y) + (f3.x + f3.y);
                se += __shfl_xor_sync(0xffffffffu, se, 1);
                se += __shfl_xor_sync(0xffffffffu, se, 2);
                if (t4 == 0) lsesum += (double)(mx2 * LN2_F + __logf(se));

                // stage lp = y2*ln2 - lpi (padded stride 68; STS.64 aligned)
                float* srow = stg + (8 * h + g) * 68 + 2 * t4;
                #pragma unroll
                for (int j = 0; j < 8; j++) {
                    int col = 8 * j + 2 * t4;
                    float l0 = fmaf(y2[2*j],   LN2_F, -lpi_s[col]);
                    float l1 = fmaf(y2[2*j+1], LN2_F, -lpi_s[col+1]);
                    *(float2*)(srow + 8 * j) = make_float2(l0, l1);
                }
            }
            __syncwarp();
            // coalesced streaming copy-out of 16 rows (out never re-read)
            float* ob = out + 65 + (size_t)(row0 + 16 * u) * Kk;
            #pragma unroll
            for (int i = 0; i < 32; i++) {
                int idx = i * 32 + lane;
                __stcs(ob + idx, stg[(idx >> 6) * 68 + (idx & 63)]);
            }
            __syncwarp();
        }
    }

    // ---- loss reduce + last-CTA finalize (deterministic replay reset) ----
    #pragma unroll
    for (int s = 16; s; s >>= 1)
        lsesum += __shfl_xor_sync(0xffffffffu, lsesum, s);
    if (lane == 0) wsum[wid] = lsesum;
    __syncthreads();
    if (tid == 0) {
        double bsum = 0.0;
        #pragma unroll
        for (int w = 0; w < TPB / 32; w++) bsum += wsum[w];
        atomicAdd(&g_lse, bsum);
        __threadfence();
        unsigned int old = atomicAdd(&g_count, 1u);
        if (old == GRID - 1) {
            __threadfence();
            double total = atomicAdd(&g_lse, 0.0);
            out[0] = (float)((double)kl_s * (double)Nn - total);
            g_lse   = 0.0;
            g_tile  = 0u;
            g_count = 0u;
        }
    }
}

// ---------------------------------------------------------------------------
extern "C" void kernel_launch(void* const* d_in, const int* in_sizes, int n_in,
                              void* d_out, int out_size)
{
    const float* X  = (const float*)d_in[0];
    const float* u  = (const float*)d_in[1];
    const float* pl = (const float*)d_in[2];
    const float* mu = (const float*)d_in[3];
    const float* lv = (const float*)d_in[4];
    const float* pi = (const float*)d_in[5];
    const float* pp = (const float*)d_in[6];
    float* out = (float*)d_out;

    cudaFuncSetAttribute(gmm_kernel,
                         cudaFuncAttributeMaxDynamicSharedMemorySize, SMEM_BYTES);

    gmm_kernel<<<GRID, TPB, SMEM_BYTES>>>(X, u, pl, mu, lv, pi, pp, out);
}